// round 1
// baseline (speedup 1.0000x reference)
#include <cuda_runtime.h>
#include <math.h>

// Shapes (fixed per problem)
#define BATCH 2
#define SEQ   2048
#define CDIM  1024
#define HEADS 16
#define HD    64          // head dim
#define SCALE 0.125f      // 64^-0.5

#define BHN   (BATCH*HEADS)            // 32
#define ROWS  (BATCH*SEQ)              // 4096 gemm rows
#define QKVN  (3*CDIM)                 // 3072

// scratch: Q,K,V in (B,H,N,D) layout + attn2gcn fallback
__device__ float g_Q[BATCH*HEADS*SEQ*HD];
__device__ float g_K[BATCH*HEADS*SEQ*HD];
__device__ float g_V[BATCH*HEADS*SEQ*HD];
__device__ float g_att_fallback[BATCH*SEQ*CDIM];

// ---------------------------------------------------------------------------
// Kernel 1: QKV GEMM  (4096 x 1024) @ (1024 x 3072), scatter into g_Q/g_K/g_V
// 128x128 block tile, BK=16, 8x8 per thread, 256 threads.
// ---------------------------------------------------------------------------
__global__ __launch_bounds__(256) void qkv_gemm(const float* __restrict__ X,
                                                const float* __restrict__ W) {
    __shared__ float As[16][128];
    __shared__ float Bs[16][128];

    const int tid = threadIdx.x;
    const int m0 = blockIdx.y * 128;
    const int n0 = blockIdx.x * 128;

    float acc[8][8];
#pragma unroll
    for (int i = 0; i < 8; i++)
#pragma unroll
        for (int j = 0; j < 8; j++) acc[i][j] = 0.f;

    const int tr = (tid >> 4) * 8;
    const int tc = (tid & 15) * 8;

    for (int k0 = 0; k0 < CDIM; k0 += 16) {
#pragma unroll
        for (int i = 0; i < 2; i++) {
            int f4 = tid + i * 256;
            int row = f4 >> 2;
            int kc = (f4 & 3) * 4;
            float4 a = *(const float4*)&X[(size_t)(m0 + row) * CDIM + k0 + kc];
            As[kc + 0][row] = a.x;
            As[kc + 1][row] = a.y;
            As[kc + 2][row] = a.z;
            As[kc + 3][row] = a.w;
        }
#pragma unroll
        for (int i = 0; i < 2; i++) {
            int f4 = tid + i * 256;
            int krow = f4 >> 5;
            int col = (f4 & 31) * 4;
            *(float4*)&Bs[krow][col] =
                *(const float4*)&W[(size_t)(k0 + krow) * QKVN + n0 + col];
        }
        __syncthreads();

#pragma unroll
        for (int kk = 0; kk < 16; kk++) {
            float ar[8], br[8];
            *(float4*)&ar[0] = *(float4*)&As[kk][tr];
            *(float4*)&ar[4] = *(float4*)&As[kk][tr + 4];
            *(float4*)&br[0] = *(float4*)&Bs[kk][tc];
            *(float4*)&br[4] = *(float4*)&Bs[kk][tc + 4];
#pragma unroll
            for (int i = 0; i < 8; i++)
#pragma unroll
                for (int j = 0; j < 8; j++) acc[i][j] += ar[i] * br[j];
        }
        __syncthreads();
    }

    // Scatter epilogue: col c -> (s, h, dd). 8 consecutive cols stay in one
    // (s,h) group since tc % 8 == 0 and 8 | 64.
    const int c = n0 + tc;
    const int s = c >> 10;
    const int h = (c & 1023) >> 6;
    const int dd = c & 63;
    float* dst = (s == 0) ? g_Q : (s == 1) ? g_K : g_V;
#pragma unroll
    for (int i = 0; i < 8; i++) {
        int m = m0 + tr + i;
        int b = m >> 11;
        int n = m & 2047;
        float* p = dst + ((((size_t)b * HEADS + h) * SEQ + n) * HD + dd);
        *(float4*)p = make_float4(acc[i][0], acc[i][1], acc[i][2], acc[i][3]);
        *(float4*)(p + 4) = make_float4(acc[i][4], acc[i][5], acc[i][6], acc[i][7]);
    }
}

// ---------------------------------------------------------------------------
// Kernel 2: flash attention. 1 query row per thread, 128 rows per block.
// KV tiles of 64 rows in smem, float4 broadcast reads (LDS.128 : FFMA = 1:4).
// Chunked-16 online softmax.
// ---------------------------------------------------------------------------
__global__ __launch_bounds__(128) void flash_attn(float* __restrict__ out2) {
    __shared__ float ks[64 * HD];
    __shared__ float vs[64 * HD];

    const int tid = threadIdx.x;
    const int bh = blockIdx.y;
    const int row = blockIdx.x * 128 + tid;

    const float* qp = g_Q + ((size_t)bh * SEQ + row) * HD;
    float q[HD];
#pragma unroll
    for (int d4 = 0; d4 < 16; d4++) {
        float4 t = *(const float4*)&qp[d4 * 4];
        q[d4 * 4 + 0] = t.x * SCALE;
        q[d4 * 4 + 1] = t.y * SCALE;
        q[d4 * 4 + 2] = t.z * SCALE;
        q[d4 * 4 + 3] = t.w * SCALE;
    }

    float acc[HD];
#pragma unroll
    for (int d = 0; d < HD; d++) acc[d] = 0.f;
    float mx = -1e30f, l = 0.f;

    const float4* kbase = (const float4*)(g_K + (size_t)bh * SEQ * HD);
    const float4* vbase = (const float4*)(g_V + (size_t)bh * SEQ * HD);

    for (int kt = 0; kt < SEQ / 64; kt++) {
        const float4* ksrc = kbase + kt * (64 * HD / 4);
        const float4* vsrc = vbase + kt * (64 * HD / 4);
#pragma unroll
        for (int i = 0; i < 8; i++) {
            ((float4*)ks)[tid + i * 128] = ksrc[tid + i * 128];
            ((float4*)vs)[tid + i * 128] = vsrc[tid + i * 128];
        }
        __syncthreads();

#pragma unroll
        for (int jc = 0; jc < 4; jc++) {
            float sv[16];
#pragma unroll
            for (int j = 0; j < 16; j++) {
                const float4* kr = (const float4*)(ks + (jc * 16 + j) * HD);
                float sj = 0.f;
#pragma unroll
                for (int d4 = 0; d4 < 16; d4++) {
                    float4 kk = kr[d4];
                    sj += q[d4 * 4 + 0] * kk.x;
                    sj += q[d4 * 4 + 1] * kk.y;
                    sj += q[d4 * 4 + 2] * kk.z;
                    sj += q[d4 * 4 + 3] * kk.w;
                }
                sv[j] = sj;
            }
            float cm = mx;
#pragma unroll
            for (int j = 0; j < 16; j++) cm = fmaxf(cm, sv[j]);
            float corr = __expf(mx - cm);
            mx = cm;
            l *= corr;
#pragma unroll
            for (int j = 0; j < 16; j++) {
                sv[j] = __expf(sv[j] - cm);
                l += sv[j];
            }
#pragma unroll
            for (int d = 0; d < HD; d++) acc[d] *= corr;
#pragma unroll
            for (int j = 0; j < 16; j++) {
                const float4* vr = (const float4*)(vs + (jc * 16 + j) * HD);
                float pj = sv[j];
#pragma unroll
                for (int d4 = 0; d4 < 16; d4++) {
                    float4 vv = vr[d4];
                    acc[d4 * 4 + 0] += pj * vv.x;
                    acc[d4 * 4 + 1] += pj * vv.y;
                    acc[d4 * 4 + 2] += pj * vv.z;
                    acc[d4 * 4 + 3] += pj * vv.w;
                }
            }
        }
        __syncthreads();
    }

    const float inv = 1.f / l;
    const int b = bh >> 4;
    const int h = bh & 15;
    float* op = out2 + (((size_t)b * SEQ + row) * CDIM + h * HD);
#pragma unroll
    for (int d4 = 0; d4 < 16; d4++) {
        ((float4*)op)[d4] = make_float4(acc[d4 * 4 + 0] * inv, acc[d4 * 4 + 1] * inv,
                                        acc[d4 * 4 + 2] * inv, acc[d4 * 4 + 3] * inv);
    }
}

// ---------------------------------------------------------------------------
// Kernel 3: proj GEMM. out = (att2 + f) @ Wproj + b
// ---------------------------------------------------------------------------
__global__ __launch_bounds__(256) void proj_gemm(const float* __restrict__ att2,
                                                 const float* __restrict__ F,
                                                 const float* __restrict__ W,
                                                 const float* __restrict__ bias,
                                                 float* __restrict__ out) {
    __shared__ float As[16][128];
    __shared__ float Bs[16][128];

    const int tid = threadIdx.x;
    const int m0 = blockIdx.y * 128;
    const int n0 = blockIdx.x * 128;

    float acc[8][8];
#pragma unroll
    for (int i = 0; i < 8; i++)
#pragma unroll
        for (int j = 0; j < 8; j++) acc[i][j] = 0.f;

    const int tr = (tid >> 4) * 8;
    const int tc = (tid & 15) * 8;

    for (int k0 = 0; k0 < CDIM; k0 += 16) {
#pragma unroll
        for (int i = 0; i < 2; i++) {
            int f4 = tid + i * 256;
            int row = f4 >> 2;
            int kc = (f4 & 3) * 4;
            size_t off = (size_t)(m0 + row) * CDIM + k0 + kc;
            float4 a = *(const float4*)&att2[off];
            float4 ff = *(const float4*)&F[off];
            As[kc + 0][row] = a.x + ff.x;
            As[kc + 1][row] = a.y + ff.y;
            As[kc + 2][row] = a.z + ff.z;
            As[kc + 3][row] = a.w + ff.w;
        }
#pragma unroll
        for (int i = 0; i < 2; i++) {
            int f4 = tid + i * 256;
            int krow = f4 >> 5;
            int col = (f4 & 31) * 4;
            *(float4*)&Bs[krow][col] =
                *(const float4*)&W[(size_t)(k0 + krow) * CDIM + n0 + col];
        }
        __syncthreads();

#pragma unroll
        for (int kk = 0; kk < 16; kk++) {
            float ar[8], br[8];
            *(float4*)&ar[0] = *(float4*)&As[kk][tr];
            *(float4*)&ar[4] = *(float4*)&As[kk][tr + 4];
            *(float4*)&br[0] = *(float4*)&Bs[kk][tc];
            *(float4*)&br[4] = *(float4*)&Bs[kk][tc + 4];
#pragma unroll
            for (int i = 0; i < 8; i++)
#pragma unroll
                for (int j = 0; j < 8; j++) acc[i][j] += ar[i] * br[j];
        }
        __syncthreads();
    }

    float bb[8];
    *(float4*)&bb[0] = *(const float4*)&bias[n0 + tc];
    *(float4*)&bb[4] = *(const float4*)&bias[n0 + tc + 4];
#pragma unroll
    for (int i = 0; i < 8; i++) {
        int m = m0 + tr + i;
        float* p = out + (size_t)m * CDIM + n0 + tc;
        *(float4*)p = make_float4(acc[i][0] + bb[0], acc[i][1] + bb[1],
                                  acc[i][2] + bb[2], acc[i][3] + bb[3]);
        *(float4*)(p + 4) = make_float4(acc[i][4] + bb[4], acc[i][5] + bb[5],
                                        acc[i][6] + bb[6], acc[i][7] + bb[7]);
    }
}

extern "C" void kernel_launch(void* const* d_in, const int* in_sizes, int n_in,
                              void* d_out, int out_size) {
    const float* x     = (const float*)d_in[0];
    const float* f     = (const float*)d_in[1];
    const float* Wqkv  = (const float*)d_in[2];
    const float* Wproj = (const float*)d_in[3];
    const float* bproj = (const float*)d_in[4];
    float* out = (float*)d_out;

    const size_t half = (size_t)BATCH * SEQ * CDIM;  // 4,194,304
    // attn2gcn is the second output; if out_size only covers `out`, fall back
    // to scratch (keeps kernel deterministic either way).
    float* att2;
    if ((size_t)out_size >= 2 * half) {
        att2 = out + half;
    } else {
        cudaGetSymbolAddress((void**)&att2, g_att_fallback);
    }

    qkv_gemm<<<dim3(QKVN / 128, ROWS / 128), 256>>>(x, Wqkv);
    flash_attn<<<dim3(SEQ / 128, BHN), 128>>>(att2);
    proj_gemm<<<dim3(CDIM / 128, ROWS / 128), 256>>>(att2, f, Wproj, bproj, out);
}